// round 2
// baseline (speedup 1.0000x reference)
#include <cuda_runtime.h>
#include <cuda_bf16.h>

// Problem constants (fixed by the reference)
#define BB 8
#define TT 4096
#define DD 256
#define MM 8
#define NC 128          // chunks along T
#define TC (TT / NC)    // 32 timesteps per chunk
#define D4 (DD / 4)     // 64 float4 lanes across D
#define CPB 2           // chunks per block
#define THREADS (CPB * D4)  // 128

// Scratch (allocation-free rule: __device__ globals)
__device__ float g_Lend[BB * NC * MM * DD];  // per-chunk local endpoint (from s=0)
__device__ float g_Sin [BB * NC * MM * DD];  // per-chunk incoming state
__device__ float g_P   [BB * NC * MM];       // per-chunk decay product

// ---------------------------------------------------------------------------
// Build alpha[CPB][TC][MM] tile in smem for this block's chunks.
// ---------------------------------------------------------------------------
__device__ __forceinline__ void build_alpha(
    const float* __restrict__ delta, const float* __restrict__ tau,
    int chunk0, float (*s_alpha)[TC][MM], float (*s_dt)[TC], float* s_rtau)
{
    int tid = threadIdx.x;
    if (tid < MM) s_rtau[tid] = 1.0f / tau[tid];
    if (tid < CPB * TC) {
        int cc = tid >> 5;         // /TC
        int t  = tid & (TC - 1);
        int g  = chunk0 + cc;
        int b  = g / NC, c = g % NC;
        int gt = c * TC + t;
        float dt = 0.0f;
        if (gt > 0)
            dt = fmaxf(delta[b * TT + gt] - delta[b * TT + gt - 1], 0.0f);
        s_dt[cc][t] = dt;
    }
    __syncthreads();
#pragma unroll
    for (int i = tid; i < CPB * TC * MM; i += THREADS) {
        int cc = i >> 8;           // /(TC*MM)
        int t  = (i >> 3) & (TC - 1);
        int m  = i & (MM - 1);
        s_alpha[cc][t][m] = __expf(-s_dt[cc][t] * s_rtau[m]);
    }
    __syncthreads();
}

// ---------------------------------------------------------------------------
// Pass 1: per-chunk carries. grid = B*NC/CPB blocks, 128 threads.
// Thread = (local chunk, d4). State: 8 x float4 in registers.
// ---------------------------------------------------------------------------
__global__ __launch_bounds__(THREADS) void carry_kernel(
    const float* __restrict__ x,
    const float* __restrict__ delta,
    const float* __restrict__ tau)
{
    __shared__ float s_rtau[MM];
    __shared__ float s_dt[CPB][TC];
    __shared__ float s_alpha[CPB][TC][MM];

    int chunk0 = blockIdx.x * CPB;
    int tid = threadIdx.x;
    int lc = tid >> 6;             // local chunk
    int d4 = tid & (D4 - 1);

    build_alpha(delta, tau, chunk0, s_alpha, s_dt, s_rtau);

    int g = chunk0 + lc;
    int b = g / NC, c = g % NC;

    float4 s[MM];
#pragma unroll
    for (int m = 0; m < MM; m++) s[m] = make_float4(0.f, 0.f, 0.f, 0.f);

    const float4* xp = (const float4*)(x + ((size_t)b * TT + c * TC) * DD) + d4;

    float4 xv = xp[0];
#pragma unroll 8
    for (int t = 0; t < TC; t++) {
        float4 xn;
        if (t + 1 < TC) xn = xp[(size_t)(t + 1) * (DD / 4)];
#pragma unroll
        for (int m = 0; m < MM; m++) {
            float a = s_alpha[lc][t][m];
            s[m].x = fmaf(a, s[m].x - xv.x, xv.x);
            s[m].y = fmaf(a, s[m].y - xv.y, xv.y);
            s[m].z = fmaf(a, s[m].z - xv.z, xv.z);
            s[m].w = fmaf(a, s[m].w - xv.w, xv.w);
        }
        xv = xn;
    }

    float4* Lp = (float4*)(g_Lend + ((size_t)g * MM) * DD) + d4;
#pragma unroll
    for (int m = 0; m < MM; m++) Lp[(size_t)m * (DD / 4)] = s[m];

    // Per-(chunk,m) decay products: 16 threads, 32 serial mults each.
    if (tid < CPB * MM) {
        int cc = tid >> 3, m = tid & (MM - 1);
        float p = 1.0f;
#pragma unroll
        for (int t = 0; t < TC; t++) p *= s_alpha[cc][t][m];
        g_P[(chunk0 + cc) * MM + m] = p;
    }
}

// ---------------------------------------------------------------------------
// Pass 2: sequential composition of chunk carries. grid = B*M blocks, 64 thr.
// P preloaded to smem; Lend loads batched by unroll so the serial FMA chain
// doesn't pay L2 latency every step.
// ---------------------------------------------------------------------------
__global__ __launch_bounds__(D4) void scan_kernel()
{
    __shared__ float sp[NC];
    int b = blockIdx.x / MM;
    int m = blockIdx.x % MM;
    int tid = threadIdx.x;

    for (int i = tid; i < NC; i += D4)
        sp[i] = g_P[(b * NC + i) * MM + m];
    __syncthreads();

    float4 s = make_float4(0.f, 0.f, 0.f, 0.f);
#pragma unroll 8
    for (int c = 0; c < NC; c++) {
        size_t idx4 = ((size_t)(b * NC + c) * MM + m) * (DD / 4) + tid;
        ((float4*)g_Sin)[idx4] = s;
        float p = sp[c];
        float4 L = ((const float4*)g_Lend)[idx4];
        s.x = fmaf(p, s.x, L.x);
        s.y = fmaf(p, s.y, L.y);
        s.z = fmaf(p, s.z, L.z);
        s.w = fmaf(p, s.w, L.w);
    }
}

// ---------------------------------------------------------------------------
// Pass 3: full scan seeded with S_in, write all outputs (STG.128, coalesced).
// ---------------------------------------------------------------------------
__global__ __launch_bounds__(THREADS) void final_kernel(
    const float* __restrict__ x,
    const float* __restrict__ delta,
    const float* __restrict__ tau,
    float* __restrict__ out)
{
    __shared__ float s_rtau[MM];
    __shared__ float s_dt[CPB][TC];
    __shared__ float s_alpha[CPB][TC][MM];

    int chunk0 = blockIdx.x * CPB;
    int tid = threadIdx.x;
    int lc = tid >> 6;
    int d4 = tid & (D4 - 1);

    build_alpha(delta, tau, chunk0, s_alpha, s_dt, s_rtau);

    int g = chunk0 + lc;
    int b = g / NC, c = g % NC;

    float4 s[MM];
    const float4* Sp = (const float4*)(g_Sin + ((size_t)g * MM) * DD) + d4;
#pragma unroll
    for (int m = 0; m < MM; m++) s[m] = Sp[(size_t)m * (DD / 4)];

    const float4* xp = (const float4*)(x + ((size_t)b * TT + c * TC) * DD) + d4;
    float4* op = (float4*)(out + ((size_t)b * TT + c * TC) * (MM * DD)) + d4;

    float4 xv = xp[0];
#pragma unroll 4
    for (int t = 0; t < TC; t++) {
        float4 xn;
        if (t + 1 < TC) xn = xp[(size_t)(t + 1) * (DD / 4)];
        float4* ot = op + (size_t)t * (MM * DD / 4);
#pragma unroll
        for (int m = 0; m < MM; m++) {
            float a = s_alpha[lc][t][m];
            s[m].x = fmaf(a, s[m].x - xv.x, xv.x);
            s[m].y = fmaf(a, s[m].y - xv.y, xv.y);
            s[m].z = fmaf(a, s[m].z - xv.z, xv.z);
            s[m].w = fmaf(a, s[m].w - xv.w, xv.w);
            ot[(size_t)m * (DD / 4)] = s[m];
        }
        xv = xn;
    }
}

// ---------------------------------------------------------------------------
extern "C" void kernel_launch(void* const* d_in, const int* in_sizes, int n_in,
                              void* d_out, int out_size)
{
    const float* x     = (const float*)d_in[0];  // [B,T,D]
    const float* delta = (const float*)d_in[1];  // [B,T]
    const float* tau   = (const float*)d_in[2];  // [M]
    float* out = (float*)d_out;                  // [B,T,M*D]

    carry_kernel<<<BB * NC / CPB, THREADS>>>(x, delta, tau);
    scan_kernel<<<BB * MM, D4>>>();
    final_kernel<<<BB * NC / CPB, THREADS>>>(x, delta, tau, out);
}